// round 5
// baseline (speedup 1.0000x reference)
#include <cuda_runtime.h>
#include <cuda_bf16.h>
#include <cstdint>

// Problem shape (fixed by dataset)
#define BB 64
#define LL 256
#define TT 1600
#define NEGV (-1e30f)
#define E_TOTAL (BB * LL * TT)          // 26,214,400
#define NE_BLOCKS 25600                 // elementwise blocks: 25600*256 = E_TOTAL/4
#define TC 16                           // time-chunk staged in smem
#define SROW 17                         // smem row stride (floats)

__device__ float g_alpha_last[BB];
__device__ unsigned int g_done_ctr = 0;

// logaddexp(x,y) + lp, with (m+lp) off the exp/log chain.
__device__ __forceinline__ float lae_add(float x, float y, float lp)
{
    float m = fmaxf(x, y);
    float d = fminf(x, y) - m;          // <= 0, finite; EX2 underflows to 0 safely
    float s = m + lp;                   // runs parallel to exp/log chain
    return s + __logf(1.0f + __expf(d));
}

// ---------------------------------------------------------------------------
// Fused kernel.
//   blocks [0, BB): recursion. 4 warps, 96 label-slots per warp (3/thread):
//     warp w carries labels [64w-32, 64w+64); owned region [64w, 64w+64).
//     Wrongness from the fake-NEG left edge advances 1 label/step, so the
//     owned region stays exact for 32 steps -> halo refreshed every 2 chunks
//     at the (already required) cp.async chunk barrier. NO per-step barrier.
//   blocks [BB, ...): elementwise log(probs+1e-30) -> out matrix.
// ---------------------------------------------------------------------------
__global__ void __launch_bounds__(256)
k_fused(const float* __restrict__ probs,
        const int* __restrict__ text_lengths,
        const int* __restrict__ mel_lengths,
        float* __restrict__ out)
{
    __shared__ float sbuf[2][LL * SROW];   // 2 x 256 x 17 floats = 34,816 B
    __shared__ float hbuf[4][32];          // halo exchange

    if (blockIdx.x >= BB) {
        // ---------------- elementwise role ----------------
        unsigned m = (blockIdx.x - BB) * 256u + threadIdx.x;
        if (m == 0) {
            out[1] = __logf(__ldg(probs + 0) + 1e-30f);
            out[2] = __logf(__ldg(probs + 1) + 1e-30f);
            out[3] = __logf(__ldg(probs + 2) + 1e-30f);
            out[(size_t)E_TOTAL] = __logf(__ldg(probs + E_TOTAL - 1) + 1e-30f);
        } else {
            float4 v = __ldg(reinterpret_cast<const float4*>(probs) + m);
            float prev = __ldg(probs + 4 * (size_t)m - 1);   // L1 hit
            float4 o;
            o.x = __logf(prev + 1e-30f);
            o.y = __logf(v.x + 1e-30f);
            o.z = __logf(v.y + 1e-30f);
            o.w = __logf(v.z + 1e-30f);
            *reinterpret_cast<float4*>(out + 4 * (size_t)m) = o;
        }
        return;
    }

    // ---------------- recursion role ----------------
    const int b   = blockIdx.x;
    const int tid = threadIdx.x;
    if (tid >= 128) return;

    const int tgt_t = __ldg(mel_lengths + b)  - 1;
    const int tgt_l = __ldg(text_lengths + b) - 1;
    const int warp  = tid >> 5;
    const int lane  = tid & 31;
    const int Wb    = 64 * warp - 32;            // warp's first (halo) label

    // Label rows for this thread's three slots
    const int r0 = Wb + 3 * lane;
    const int r1 = r0 + 1, r2 = r0 + 2;
    const bool v0 = (r0 >= 0), v1 = (r1 >= 0), v2 = (r2 >= 0);
    const int cr0 = v0 ? r0 : 0, cr1 = v1 ? r1 : 0, cr2 = v2 ? r2 : 0;

    const float* pbase = probs + (size_t)b * LL * TT;
    const uint32_t sb_u32 = (uint32_t)__cvta_generic_to_shared(&sbuf[0][0]);

    // Stage chunk 0 (t=0..15): 256 rows x 16 cols, coalesced 4B cp.async.
#pragma unroll
    for (int j = 0; j < TC; ++j) {
#pragma unroll
        for (int h = 0; h < 2; ++h) {
            int o   = j * 256 + h * 128 + tid;
            int row = o >> 4, col = o & 15;
            uint32_t sa = sb_u32 + (uint32_t)(row * SROW + col) * 4u;
            const float* g = pbase + (size_t)row * TT + col;
            asm volatile("cp.async.ca.shared.global [%0], [%1], 4;"
                         :: "r"(sa), "l"(g));
        }
    }
    asm volatile("cp.async.commit_group;");
    asm volatile("cp.async.wait_group 0;");
    __syncthreads();

    float a0 = NEGV, a1 = NEGV, a2 = NEGV;
    // alpha[0][label 0]: label 0 = slot 32 of warp 0 = (lane 10, s=2)
    if (warp == 0 && lane == 10) a2 = __logf(sbuf[0][0] + 1e-30f);

    const int nchunks = tgt_t / TC + 1;

    for (int c = 0; c < nchunks; ++c) {
        const int  cb = c & 1, nb = cb ^ 1;
        const int  g1 = TC * (c + 1);
        const bool do_stage = (g1 <= tgt_t);
        const uint32_t snb = sb_u32 + (uint32_t)(nb * LL * SROW) * 4u;

#pragma unroll
        for (int j = 0; j < TC; ++j) {
            if (do_stage) {
#pragma unroll
                for (int h = 0; h < 2; ++h) {
                    int o   = j * 256 + h * 128 + tid;
                    int row = o >> 4, col = o & 15;
                    int tc2 = g1 + col; if (tc2 > TT - 1) tc2 = TT - 1;  // clamp
                    uint32_t sa = snb + (uint32_t)(row * SROW + col) * 4u;
                    const float* g = pbase + (size_t)row * TT + tc2;
                    asm volatile("cp.async.ca.shared.global [%0], [%1], 4;"
                                 :: "r"(sa), "l"(g));
                }
            }
            const int t = TC * c + j;
            if (t >= 1 && t <= tgt_t) {              // block-uniform
                float lp0 = __logf(sbuf[cb][cr0 * SROW + j] + 1e-30f);
                float lp1 = __logf(sbuf[cb][cr1 * SROW + j] + 1e-30f);
                float lp2 = __logf(sbuf[cb][cr2 * SROW + j] + 1e-30f);

                float sh   = __shfl_up_sync(0xffffffffu, a2, 1);
                float left = (lane == 0) ? NEGV : sh;   // degradation front

                float n0 = lae_add(a0, left, lp0);
                float n1 = lae_add(a1, a0,   lp1);
                float n2 = lae_add(a2, a1,   lp2);
                a0 = v0 ? n0 : NEGV;
                a1 = v1 ? n1 : NEGV;
                a2 = v2 ? n2 : NEGV;
            }
        }

        // Chunk boundary. Every 2nd chunk (= every 32 steps): halo refresh.
        const bool halo = ((c & 1) == 1);
        if (halo) {
            const int s0 = 3 * lane;
            if (s0     >= 64) hbuf[warp][s0 - 64] = a0;
            if (s0 + 1 >= 64) hbuf[warp][s0 - 63] = a1;
            if (s0 + 2 >= 64) hbuf[warp][s0 - 62] = a2;
        }
        asm volatile("cp.async.commit_group;");
        asm volatile("cp.async.wait_group 0;");
        __syncthreads();
        if (halo && warp > 0) {
            const int s0 = 3 * lane;
            if (s0     < 32) a0 = hbuf[warp - 1][s0];
            if (s0 + 1 < 32) a1 = hbuf[warp - 1][s0 + 1];
            if (s0 + 2 < 32) a2 = hbuf[warp - 1][s0 + 2];
        }
    }

    // Extract alpha at (tgt_t, tgt_l). Owned slot = (tgt_l & 63) + 32.
    {
        const int wt   = tgt_l >> 6;
        const int slot = (tgt_l & 63) + 32;
        if (warp == wt && lane == slot / 3) {
            const int s = slot - 3 * lane;
            g_alpha_last[b] = (s == 0) ? a0 : ((s == 1) ? a1 : a2);
        }
    }
    __syncthreads();

    // Last recursion block to finish reduces: loss = -mean(alpha_last)
    if (tid == 0) {
        __threadfence();
        unsigned old = atomicAdd(&g_done_ctr, 1u);
        if (old == BB - 1) {
            g_done_ctr = 0;                    // reset for next graph replay
            __threadfence();
            float s = 0.0f;
#pragma unroll
            for (int i = 0; i < BB; ++i) s += g_alpha_last[i];
            out[0] = -s * (1.0f / BB);
        }
    }
}

// ---------------------------------------------------------------------------
extern "C" void kernel_launch(void* const* d_in, const int* in_sizes, int n_in,
                              void* d_out, int out_size)
{
    const float* probs        = (const float*)d_in[0];
    // d_in[1] = melspec (unused by the computation)
    const int*   text_lengths = (const int*)d_in[2];
    const int*   mel_lengths  = (const int*)d_in[3];

    float* out = (float*)d_out;   // out[0] = loss, out[1..E_TOTAL] = log matrix

    k_fused<<<BB + NE_BLOCKS, 256>>>(probs, text_lengths, mel_lengths, out);
    (void)in_sizes; (void)n_in; (void)out_size;
}

// round 6
// speedup vs baseline: 1.5505x; 1.5505x over previous
#include <cuda_runtime.h>
#include <cuda_bf16.h>
#include <cstdint>

// Problem shape (fixed by dataset)
#define BB 64
#define LL 256
#define TT 1600
#define NEGV (-1e30f)
#define E_TOTAL (BB * LL * TT)
#define TC 32                       // time-chunk
#define SROW 33                     // smem row stride (floats), odd -> conflict-free
#define NCH (TT / TC)               // 50 chunks
#define BUF_FLOATS (LL * SROW)      // 8448 floats per buffer
#define SMEM_BYTES (3 * BUF_FLOATS * 4)   // 101,376 B (triple buffer)

__device__ float g_alpha_last[BB];
__device__ unsigned int g_done_ctr = 0;

// logaddexp(x,y) + lp, with (m+lp) off the exp/log chain.
__device__ __forceinline__ float lae_add(float x, float y, float lp)
{
    float m = fmaxf(x, y);
    float d = fminf(x, y) - m;          // <= 0; EX2 underflows to 0 safely
    float s = m + lp;                   // parallel to exp/log chain
    return s + __logf(1.0f + __expf(d));
}

extern __shared__ float sbuf[];         // 3 buffers of [LL][SROW]

// ---------------------------------------------------------------------------
// One block per batch. 8 warps:
//   warps 0-3 (recursion): R5 halo layout — warp w carries labels
//     [64w-32, 64w+64), 3 slots/thread, owned region exact for 32 steps;
//     halo refreshed at every chunk barrier. lp values read PRE-LOGGED
//     from smem (no MUFU for lp in the serial loop).
//   warps 4-7 (convert): cp.async-stage raw probs chunks (triple buffered),
//     convert raw->log in smem, and write the log chunk to the output
//     matrix (this IS the elementwise pass — coalesced 128B row segments).
// ---------------------------------------------------------------------------
__global__ void __launch_bounds__(256, 1)
k_mdn(const float* __restrict__ probs,
      const int* __restrict__ text_lengths,
      const int* __restrict__ mel_lengths,
      float* __restrict__ out)
{
    __shared__ float hbuf[2][4][32];    // halo exchange, chunk-parity buffered

    const int b    = blockIdx.x;
    const int tid  = threadIdx.x;
    const int warp = tid >> 5;
    const int lane = tid & 31;

    const int tgt_t = __ldg(mel_lengths  + b) - 1;
    const int tgt_l = __ldg(text_lengths + b) - 1;

    const float* pbase = probs + (size_t)b * LL * TT;
    float*       obase = out + 1 + (size_t)b * LL * TT;

    const uint32_t s_u32 = (uint32_t)__cvta_generic_to_shared(sbuf);
    const bool is_conv = (warp >= 4);
    const int  wc = warp - 4;           // convert warp id (0..3), rows [64wc,64wc+64)

    // ---------------- prologue: land chunks 0,1; convert chunk 0 ----------------
    if (is_conv) {
#pragma unroll
        for (int c0 = 0; c0 < 2; ++c0) {
            for (int i = 0; i < 64; ++i) {
                int row = 64 * wc + i;
                uint32_t sa = s_u32 + (uint32_t)(c0 * BUF_FLOATS + row * SROW + lane) * 4u;
                const float* g = pbase + (size_t)row * TT + c0 * TC + lane;
                asm volatile("cp.async.ca.shared.global [%0], [%1], 4;"
                             :: "r"(sa), "l"(g));
            }
            asm volatile("cp.async.commit_group;");
        }
        asm volatile("cp.async.wait_group 1;");      // chunk 0 landed
        for (int i = 0; i < 64; ++i) {
            int row = 64 * wc + i;
            float v  = sbuf[row * SROW + lane];
            float lg = __logf(v + 1e-30f);
            sbuf[row * SROW + lane] = lg;            // logged, in place
            obase[(size_t)row * TT + lane] = lg;     // elementwise output, t=lane
        }
    }
    __syncthreads();

    // Recursion state: 3 slots/thread (R5 layout)
    const int Wb = 64 * warp - 32;
    const int r0 = Wb + 3 * lane, r1 = r0 + 1, r2 = r0 + 2;
    const bool v0 = (r0 >= 0), v1 = (r1 >= 0), v2 = (r2 >= 0);
    const int cr0 = v0 ? r0 : 0, cr1 = v1 ? r1 : 0, cr2 = v2 ? r2 : 0;

    float a0 = NEGV, a1 = NEGV, a2 = NEGV;
    if (warp == 0 && lane == 10) a2 = sbuf[0];       // logged lp[0][0] (slot 32 = label 0)

    // ---------------- main loop over 50 chunks ----------------
    for (int c = 0; c < NCH; ++c) {
        const int cb = c % 3, nb = (c + 1) % 3, fb = (c + 2) % 3;

        if (is_conv) {
            // (i) stage raw chunk c+2 into fb
            if (c + 2 < NCH) {
                const int t0f = (c + 2) * TC;
                for (int i = 0; i < 64; ++i) {
                    int row = 64 * wc + i;
                    uint32_t sa = s_u32 + (uint32_t)(fb * BUF_FLOATS + row * SROW + lane) * 4u;
                    const float* g = pbase + (size_t)row * TT + t0f + lane;
                    asm volatile("cp.async.ca.shared.global [%0], [%1], 4;"
                                 :: "r"(sa), "l"(g));
                }
            }
            asm volatile("cp.async.commit_group;");      // group even if empty
            asm volatile("cp.async.wait_group 1;");      // chunk c+1 landed
            // (ii) convert chunk c+1 in nb: raw -> log (smem) + write to out
            if (c + 1 < NCH) {
                const int t0n = (c + 1) * TC;
                float* bufn = sbuf + nb * BUF_FLOATS;
                for (int i = 0; i < 64; ++i) {
                    int row = 64 * wc + i;
                    float v  = bufn[row * SROW + lane];
                    float lg = __logf(v + 1e-30f);
                    bufn[row * SROW + lane] = lg;
                    obase[(size_t)row * TT + t0n + lane] = lg;
                }
            }
        } else {
            // recursion: 32 steps on logged chunk cb
            const float* bufc = sbuf + cb * BUF_FLOATS;
            const int tbase = c * TC;
            if (tbase <= tgt_t) {
#pragma unroll
                for (int j = 0; j < TC; ++j) {
                    const int t = tbase + j;
                    if (t >= 1 && t <= tgt_t) {          // block-uniform
                        float lp0 = bufc[cr0 * SROW + j];
                        float lp1 = bufc[cr1 * SROW + j];
                        float lp2 = bufc[cr2 * SROW + j];

                        float sh   = __shfl_up_sync(0xffffffffu, a2, 1);
                        float left = (lane == 0) ? NEGV : sh;   // degradation front

                        float n0 = lae_add(a0, left, lp0);
                        float n1 = lae_add(a1, a0,   lp1);
                        float n2 = lae_add(a2, a1,   lp2);
                        a0 = v0 ? n0 : NEGV;
                        a1 = v1 ? n1 : NEGV;
                        a2 = v2 ? n2 : NEGV;
                    }
                }
            }
            // halo publish: owned offsets [32,64) = labels [64w+32, 64w+64)
            const int s0 = 3 * lane;
            float* hw = &hbuf[c & 1][warp][0];
            if (s0     >= 64) hw[s0 - 64] = a0;
            if (s0 + 1 >= 64) hw[s0 - 63] = a1;
            if (s0 + 2 >= 64) hw[s0 - 62] = a2;
        }

        __syncthreads();

        if (!is_conv && warp > 0) {        // halo refresh from left warp
            const int s0 = 3 * lane;
            const float* hr = &hbuf[c & 1][warp - 1][0];
            if (s0     < 32) a0 = hr[s0];
            if (s0 + 1 < 32) a1 = hr[s0 + 1];
            if (s0 + 2 < 32) a2 = hr[s0 + 2];
        }
    }

    // ---------------- extract alpha(tgt_t, tgt_l) ----------------
    if (!is_conv) {
        const int wt   = tgt_l >> 6;
        const int slot = (tgt_l & 63) + 32;          // owned slot index
        if (warp == wt && lane == slot / 3) {
            const int s = slot - 3 * lane;
            g_alpha_last[b] = (s == 0) ? a0 : ((s == 1) ? a1 : a2);
        }
    }
    __syncthreads();

    // last block to finish computes loss = -mean(alpha_last)
    if (tid == 0) {
        __threadfence();
        unsigned old = atomicAdd(&g_done_ctr, 1u);
        if (old == BB - 1) {
            g_done_ctr = 0;                          // reset for graph replay
            __threadfence();
            float s = 0.0f;
#pragma unroll
            for (int i = 0; i < BB; ++i) s += g_alpha_last[i];
            out[0] = -s * (1.0f / BB);
        }
    }
}

// ---------------------------------------------------------------------------
extern "C" void kernel_launch(void* const* d_in, const int* in_sizes, int n_in,
                              void* d_out, int out_size)
{
    const float* probs        = (const float*)d_in[0];
    // d_in[1] = melspec (unused by the computation)
    const int*   text_lengths = (const int*)d_in[2];
    const int*   mel_lengths  = (const int*)d_in[3];

    float* out = (float*)d_out;   // out[0] = loss, out[1..E_TOTAL] = log matrix

    static bool attr_set = false;
    if (!attr_set) {
        cudaFuncSetAttribute(k_mdn, cudaFuncAttributeMaxDynamicSharedMemorySize,
                             SMEM_BYTES);
        attr_set = true;
    }
    k_mdn<<<BB, 256, SMEM_BYTES>>>(probs, text_lengths, mel_lengths, out);
    (void)in_sizes; (void)n_in; (void)out_size;
}